// round 8
// baseline (speedup 1.0000x reference)
#include <cuda_runtime.h>
#include <cuda_bf16.h>

#define NTOT 524288
#define DIM  128
#define S    128
#define G    (NTOT / S)
#define MARGIN   2.0f
#define K_MARGIN 0.02f
#define EPS      1e-6f

// Per-group scratch + completion counter (static device allocation — allowed).
__device__ float g_loss[G];
__device__ float g_sumb[G];
__device__ float g_sump[G];
__device__ int   g_cntb[G];
__device__ int   g_done = 0;   // reset by last CTA each launch -> replay-safe

// ---------------------------------------------------------------------------
// Kernel 1: d[i] = 1 - dot(z_r[i], z_v[i]).  One warp per row, float4 loads.
// EXACT config that measured 85.3% DRAM / 6.76 TB/s in round 1 (16 regs).
// ---------------------------------------------------------------------------
__global__ void __launch_bounds__(256) dot_kernel(
    const float4* __restrict__ zr, const float4* __restrict__ zv,
    float* __restrict__ dout)
{
    int gw   = (blockIdx.x * blockDim.x + threadIdx.x) >> 5;   // row id
    int lane = threadIdx.x & 31;
    size_t off = (size_t)gw * 32 + lane;                       // 32 float4 per row
    float4 a = zr[off];
    float4 b = zv[off];
    float s = a.x * b.x + a.y * b.y + a.z * b.z + a.w * b.w;
    #pragma unroll
    for (int o = 16; o; o >>= 1) s += __shfl_xor_sync(0xffffffffu, s, o);
    if (lane == 0) dout[gw] = 1.0f - s;
}

// ---------------------------------------------------------------------------
// Batched block-wide sum over 256 threads (8 warps). All threads get results.
// ---------------------------------------------------------------------------
template<int K>
__device__ __forceinline__ void blockSumK(float* v, float (*red)[8])
{
    #pragma unroll
    for (int k = 0; k < K; k++)
        #pragma unroll
        for (int o = 16; o; o >>= 1)
            v[k] += __shfl_xor_sync(0xffffffffu, v[k], o);
    int w = threadIdx.x >> 5;
    if ((threadIdx.x & 31) == 0)
        #pragma unroll
        for (int k = 0; k < K; k++) red[k][w] = v[k];
    __syncthreads();
    #pragma unroll
    for (int k = 0; k < K; k++)
        v[k] = (red[k][0] + red[k][1]) + (red[k][2] + red[k][3])
             + (red[k][4] + red[k][5]) + (red[k][6] + red[k][7]);
    __syncthreads();
}

// ---------------------------------------------------------------------------
// Kernel 2: one CTA (256 threads) per group; d comes from hot L2.
//  - label sums, corr_loss (ddof=1, eps, zero-std guards)
//  - STABLE counting sort by var_len (matches jnp.argsort stable)
//  - neigh_viol, rank_loss (analytic pair count via tie-run end, 2-way split)
//  - last CTA: deterministic double-precision finalize -> out[0], out[1]
// ---------------------------------------------------------------------------
__global__ void __launch_bounds__(256) group_kernel(
    const int* __restrict__ var_lens, const int* __restrict__ labels,
    float* __restrict__ out)
{
    __shared__ int   sv[S];      // v (original order)
    __shared__ float sds[S];     // d sorted by v (stable)
    __shared__ int   se[S];      // tie-run end (exclusive) at sorted position
    __shared__ int   cnt[101];   // counting-sort bins
    __shared__ int   P[101];     // exclusive bin prefix; P[100] = S
    __shared__ float red[5][8];
    __shared__ int   isLast;

    const int g   = blockIdx.x;
    const int tid = threadIdx.x;
    const float* dvec = out + 2;

    if (tid < 101) cnt[tid] = 0;
    __syncthreads();

    const bool act = tid < S;
    int   v  = 0, lb = -1;
    float di = 0.0f;
    if (act) {
        int idx = g * S + tid;
        di = dvec[idx];            // L2 hit (2 MB, just written)
        v  = min(max(var_lens[idx], 0), 99);
        lb = labels[idx];
        sv[tid] = v;
        atomicAdd(&cnt[v], 1);
    }

    // ---- pass 1: label sums + means (5 sums, one barrier pair) ----
    float vf = act ? (float)v : 0.0f;
    float p1[5] = { lb == 0 ? di : 0.0f, lb == 1 ? di : 0.0f,
                    lb == 0 ? 1.0f : 0.0f, vf, act ? di : 0.0f };
    blockSumK<5>(p1, red);
    float sb = p1[0], sp = p1[1], cb = p1[2];
    float meanv = p1[3] * (1.0f / S);
    float meand = p1[4] * (1.0f / S);

    // ---- pass 2: variances (ddof=1) ----
    float dv0 = act ? vf - meanv : 0.0f;
    float dd0 = act ? di - meand : 0.0f;
    float p2[2] = { dv0 * dv0, dd0 * dd0 };
    blockSumK<2>(p2, red);
    float vs = sqrtf(p2[0] * (1.0f / (S - 1)));
    float ds = sqrtf(p2[1] * (1.0f / (S - 1)));
    float vz = dv0 / (vs + EPS);
    float dz = dd0 / (ds + EPS);

    // ---- pass 3: corr ----
    float p3[1] = { act ? (vz - dz) * (vz - dz) : 0.0f };
    blockSumK<1>(p3, red);
    float corr = p3[0] * (1.0f / S);
    if (!(vs > 0.0f && ds > 0.0f)) corr = 0.0f;

    // ---- bin prefix sums (serial over 100 bins) ----
    if (tid == 0) {
        int run = 0;
        #pragma unroll 4
        for (int q = 0; q < 100; q++) { P[q] = run; run += cnt[q]; }
        P[100] = run;   // == S
    }
    __syncthreads();

    // ---- stable scatter: rank among earlier equal keys ----
    if (act) {
        int rank = 0;
        #pragma unroll 8
        for (int j = 0; j < S; j++) rank += (j < tid) & (sv[j] == v);
        int pos = P[v] + rank;
        sds[pos] = di;
        se[pos]  = P[v + 1];   // end (exclusive) of this tie run
    }
    __syncthreads();

    // ---- pass 4: neigh_viol + rank_loss (3 sums, one barrier pair) ----
    float nv = (tid < S - 1) ? fmaxf(sds[tid] - sds[tid + 1] + K_MARGIN, 0.0f) : 0.0f;
    const int   i   = tid & (S - 1);
    const int   h   = tid >> 7;
    const int   e   = se[i];
    const float ddi = sds[i] + K_MARGIN;
    float viol = 0.0f;
    for (int j = e + h; j < S; j += 2)
        viol += fmaxf(ddi - sds[j], 0.0f);
    float p4[3] = { nv, h == 0 ? (float)(S - e) : 0.0f, viol };
    blockSumK<3>(p4, red);
    float neigh = p4[0] * (1.0f / (S - 1));
    float rankl = (p4[1] > 0.0f) ? p4[2] / p4[1] : 0.0f;

    if (tid == 0) {
        g_loss[g] = corr + neigh + rankl;
        g_sumb[g] = sb;
        g_sump[g] = sp;
        g_cntb[g] = (int)cb;
        __threadfence();
        int old = atomicAdd(&g_done, 1);
        isLast = (old == G - 1);
    }
    __syncthreads();

    // ---------------- last CTA finalizes ----------------
    if (isLast) {
        __shared__ double shL[256], shB[256], shP[256];
        __shared__ long long shC[256];

        double aL = 0.0, aB = 0.0, aP = 0.0;
        long long cB = 0;
        #pragma unroll 4
        for (int q = tid; q < G; q += 256) {
            aL += (double)g_loss[q];
            aB += (double)g_sumb[q];
            aP += (double)g_sump[q];
            cB += (long long)g_cntb[q];
        }
        shL[tid] = aL; shB[tid] = aB; shP[tid] = aP; shC[tid] = cB;
        __syncthreads();
        #pragma unroll
        for (int s = 128; s > 0; s >>= 1) {
            if (tid < s) {
                shL[tid] += shL[tid + s];
                shB[tid] += shB[tid + s];
                shP[tid] += shP[tid + s];
                shC[tid] += shC[tid + s];
            }
            __syncthreads();
        }
        if (tid == 0) {
            long long nb = shC[0];
            long long np = (long long)NTOT - nb;
            double mb = shB[0] / (double)(nb > 1 ? nb : 1);
            double mp = shP[0] / (double)(np > 1 ? np : 1);
            double lcdd = (nb > 0 && np > 0) ? (MARGIN + mb - mp) : 0.0;
            if (lcdd < 0.0) lcdd = 0.0;
            out[0] = (float)lcdd;
            out[1] = (float)(shL[0] / (double)G);
            g_done = 0;            // reset for next graph replay
        }
    }
}

// ---------------------------------------------------------------------------
extern "C" void kernel_launch(void* const* d_in, const int* in_sizes, int n_in,
                              void* d_out, int out_size)
{
    const float* zr       = (const float*)d_in[0];
    const float* zv       = (const float*)d_in[1];
    const int*   labels   = (const int*)d_in[2];
    // d_in[3] = groups (== i / S by construction, unused)
    const int*   var_lens = (const int*)d_in[4];
    float* out = (float*)d_out;

    dot_kernel<<<NTOT / 8, 256>>>((const float4*)zr, (const float4*)zv, out + 2);
    group_kernel<<<G, 256>>>(var_lens, labels, out);
}